// round 6
// baseline (speedup 1.0000x reference)
#include <cuda_runtime.h>
#include <cuda_bf16.h>
#include <cstdint>
#include <math.h>

#define T_SEQ   2048
#define C_EMB   4096
#define QKV_N   6144
#define FFN_N   11008
#define N_HEAD_ 32

typedef __nv_bfloat16 bf16;

// ---------------- scratch (static device globals; allocation-free) ----------------
__device__ float g_qkv[T_SEQ * QKV_N];
__device__ float g_scaling[T_SEQ * C_EMB];
__device__ float g_scale_t[N_HEAD_ * T_SEQ];
__device__ float g_resid[T_SEQ * C_EMB];
__device__ float g_gate[T_SEQ * FFN_N];

// split bf16 planes: weights
__device__ bf16 g_wq_h[QKV_N * C_EMB];  __device__ bf16 g_wq_l[QKV_N * C_EMB];
__device__ bf16 g_ws_h[C_EMB * C_EMB];  __device__ bf16 g_ws_l[C_EMB * C_EMB];
__device__ bf16 g_wp_h[C_EMB * C_EMB];  __device__ bf16 g_wp_l[C_EMB * C_EMB];
__device__ bf16 g_wg_h[FFN_N * C_EMB];  __device__ bf16 g_wg_l[FFN_N * C_EMB];
__device__ bf16 g_wu_h[FFN_N * C_EMB];  __device__ bf16 g_wu_l[FFN_N * C_EMB];
__device__ bf16 g_wd_h[C_EMB * FFN_N];  __device__ bf16 g_wd_l[C_EMB * FFN_N];
// split bf16 planes: activations
__device__ bf16 g_n1_h[T_SEQ * C_EMB];  __device__ bf16 g_n1_l[T_SEQ * C_EMB];
__device__ bf16 g_n2_h[T_SEQ * C_EMB];  __device__ bf16 g_n2_l[T_SEQ * C_EMB];
__device__ bf16 g_y_h[T_SEQ * C_EMB];   __device__ bf16 g_y_l[T_SEQ * C_EMB];
__device__ bf16 g_hb_h[T_SEQ * FFN_N];  __device__ bf16 g_hb_l[T_SEQ * FFN_N];

// ---------------- small helpers ----------------
__device__ __forceinline__ uint32_t smem_u32(const void* p) {
    return (uint32_t)__cvta_generic_to_shared(p);
}
__device__ __forceinline__ void split2(float f, bf16& h, bf16& l) {
    h = __float2bfloat16(f);
    l = __float2bfloat16(f - __bfloat162float(h));
}
__device__ __forceinline__ uint32_t pack_bf2(bf16 a, bf16 b) {
    __nv_bfloat162 p; p.x = a; p.y = b;
    return *(uint32_t*)&p;
}
__device__ __forceinline__ void cp_async16(void* smem_ptr, const void* gptr) {
    unsigned s = (unsigned)__cvta_generic_to_shared(smem_ptr);
    asm volatile("cp.async.cg.shared.global [%0], [%1], 16;" :: "r"(s), "l"(gptr));
}
#define CP_COMMIT() asm volatile("cp.async.commit_group;" ::: "memory")

#define LDSM4(r0, r1, r2, r3, addr) \
    asm volatile("ldmatrix.sync.aligned.m8n8.x4.shared.b16 {%0,%1,%2,%3}, [%4];" \
        : "=r"(r0), "=r"(r1), "=r"(r2), "=r"(r3) : "r"(addr))

__device__ __forceinline__ void mma_bf16(float* d, const uint32_t* a, uint32_t b0, uint32_t b1) {
    asm volatile(
        "mma.sync.aligned.m16n8k16.row.col.f32.bf16.bf16.f32 "
        "{%0,%1,%2,%3},{%4,%5,%6,%7},{%8,%9},{%0,%1,%2,%3};"
        : "+f"(d[0]), "+f"(d[1]), "+f"(d[2]), "+f"(d[3])
        : "r"(a[0]), "r"(a[1]), "r"(a[2]), "r"(a[3]), "r"(b0), "r"(b1));
}

// ---------------- weight / activation split kernel ----------------
__global__ __launch_bounds__(256) void split_kernel(const float* __restrict__ in,
                                                    bf16* __restrict__ hi,
                                                    bf16* __restrict__ lo) {
    const long i = ((long)blockIdx.x * 256 + threadIdx.x) * 4;
    const float4 v = *(const float4*)(in + i);
    bf16 h0, h1, h2, h3, l0, l1, l2, l3;
    split2(v.x, h0, l0); split2(v.y, h1, l1); split2(v.z, h2, l2); split2(v.w, h3, l3);
    uint2 ho = {pack_bf2(h0, h1), pack_bf2(h2, h3)};
    uint2 loo = {pack_bf2(l0, l1), pack_bf2(l2, l3)};
    *(uint2*)(hi + i) = ho;
    *(uint2*)(lo + i) = loo;
}

// ---------------- RMSNorm (fp32 in -> split bf16 planes out) ----------------
__global__ __launch_bounds__(256) void rmsnorm_split(const float* __restrict__ x,
                                                     const float* __restrict__ w,
                                                     bf16* __restrict__ oh,
                                                     bf16* __restrict__ ol) {
    const long row = blockIdx.x;
    const float* xr = x + row * C_EMB;
    const int tid = threadIdx.x;

    float4 v[4];
    float ss = 0.f;
#pragma unroll
    for (int i = 0; i < 4; i++) {
        v[i] = *(const float4*)(xr + tid * 4 + i * 1024);
        ss += v[i].x * v[i].x + v[i].y * v[i].y + v[i].z * v[i].z + v[i].w * v[i].w;
    }
#pragma unroll
    for (int o = 16; o; o >>= 1) ss += __shfl_xor_sync(0xffffffffu, ss, o);
    __shared__ float red[8];
    if ((tid & 31) == 0) red[tid >> 5] = ss;
    __syncthreads();
    float tot = red[0] + red[1] + red[2] + red[3] + red[4] + red[5] + red[6] + red[7];
    const float inv = rsqrtf(tot * (1.f / 4096.f) + 1e-5f);
#pragma unroll
    for (int i = 0; i < 4; i++) {
        float4 wv = *(const float4*)(w + tid * 4 + i * 1024);
        float o0 = v[i].x * inv * wv.x, o1 = v[i].y * inv * wv.y;
        float o2 = v[i].z * inv * wv.z, o3 = v[i].w * inv * wv.w;
        bf16 h0, h1, h2, h3, l0, l1, l2, l3;
        split2(o0, h0, l0); split2(o1, h1, l1); split2(o2, h2, l2); split2(o3, h3, l3);
        const long off = row * C_EMB + tid * 4 + i * 1024;
        uint2 ho = {pack_bf2(h0, h1), pack_bf2(h2, h3)};
        uint2 lo = {pack_bf2(l0, l1), pack_bf2(l2, l3)};
        *(uint2*)(oh + off) = ho;
        *(uint2*)(ol + off) = lo;
    }
}

// ---------------- bf16x3 mma.sync GEMM: C[M,N] = A[M,K] * W[N,K]^T ----------------
// Split-plane operands. Tile 128x128, BK=64, 3-stage cp.async ring, 8 warps.
// EPI: 0 none, 1 relu(+bias), 2 +extra, 3 silu(extra)*acc.  OUT: 0 fp32, 1 split planes.
#define STAGE_BYTES 65536   // 4 tiles (Ah,Al,Bh,Bl) * 128 rows * 128B
#define GEMM_SMEM (3 * STAGE_BYTES)

__device__ __forceinline__ void stage_tiles(char* sm, int stg,
        const bf16* __restrict__ Ah, const bf16* __restrict__ Al,
        const bf16* __restrict__ Bh, const bf16* __restrict__ Bl,
        long bm, long bn, long K, int k0, int tid) {
    const int row = tid >> 1;
    const int cb = (tid & 1) * 4;
    char* st = sm + stg * STAGE_BYTES;
    const bf16* srcs[4] = {Ah, Al, Bh, Bl};
#pragma unroll
    for (int tile = 0; tile < 4; tile++) {
        const long rb = (tile < 2) ? bm : bn;
        const char* src = (const char*)(srcs[tile] + (rb + row) * K + k0);
        char* dst = st + tile * 16384;
#pragma unroll
        for (int c = 0; c < 4; c++) {
            const int chunk = cb + c;
            const int sw = row * 128 + ((chunk ^ (row & 7)) << 4);
            cp_async16(dst + sw, src + chunk * 16);
        }
    }
}

template <int EPI, int OUT>
__global__ __launch_bounds__(256, 1)
void tc_gemm(const bf16* __restrict__ Ah, const bf16* __restrict__ Al,
             const bf16* __restrict__ Bh, const bf16* __restrict__ Bl,
             float* __restrict__ C, bf16* __restrict__ Ch, bf16* __restrict__ Cl,
             int M, int N, int K,
             const float* __restrict__ extra, const float* __restrict__ bias) {
    extern __shared__ __align__(1024) char sm[];
    const uint32_t sbase = smem_u32(sm);

    const int tid  = threadIdx.x;
    const int warp = tid >> 5;
    const int lane = tid & 31;
    const long bm = (long)blockIdx.y * 128;
    const long bn = (long)blockIdx.x * 128;
    const int wm = (warp & 1) * 64;    // 2 warps along M
    const int wn = (warp >> 1) * 32;   // 4 warps along N

    // ldmatrix lane roles
    const int ar = (lane & 7) + ((lane >> 3) & 1) * 8;  // A: row offset within m16
    const int ac = lane >> 4;                           // A: k-chunk offset (0/1)
    const int br = (lane & 7) + ((lane >> 4) & 1) * 8;  // B: row offset within n16
    const int bc = (lane >> 3) & 1;                     // B: k-chunk offset (0/1)
    const int xr = lane & 7;                            // swizzle key (row&7)

    float acc[4][4][4];
#pragma unroll
    for (int mt = 0; mt < 4; mt++)
#pragma unroll
        for (int nt = 0; nt < 4; nt++)
#pragma unroll
            for (int u = 0; u < 4; u++) acc[mt][nt][u] = 0.f;

    const int steps = K >> 6;
    stage_tiles(sm, 0, Ah, Al, Bh, Bl, bm, bn, K, 0, tid);  CP_COMMIT();
    stage_tiles(sm, 1, Ah, Al, Bh, Bl, bm, bn, K, 64, tid); CP_COMMIT();

    for (int s = 0; s < steps; ++s) {
        const int buf = s % 3;
        if (s + 1 < steps) { asm volatile("cp.async.wait_group 1;" ::: "memory"); }
        else               { asm volatile("cp.async.wait_group 0;" ::: "memory"); }
        __syncthreads();
        if (s + 2 < steps) {
            stage_tiles(sm, (s + 2) % 3, Ah, Al, Bh, Bl, bm, bn, K, (s + 2) * 64, tid);
            CP_COMMIT();
        }
        const uint32_t st = sbase + buf * STAGE_BYTES;
        const uint32_t baseAh = st + (wm + ar) * 128;
        const uint32_t baseAl = st + 16384 + (wm + ar) * 128;
        const uint32_t baseBh = st + 32768 + (wn + br) * 128;
        const uint32_t baseBl = st + 49152 + (wn + br) * 128;

#pragma unroll
        for (int kc = 0; kc < 4; ++kc) {
            const uint32_t aoff = ((((kc << 1) + ac) ^ xr) << 4);
            const uint32_t boff = ((((kc << 1) + bc) ^ xr) << 4);
            uint32_t Afh[4][4], Afl[4][4];
#pragma unroll
            for (int mt = 0; mt < 4; ++mt) {
                LDSM4(Afh[mt][0], Afh[mt][1], Afh[mt][2], Afh[mt][3], baseAh + mt * 2048 + aoff);
                LDSM4(Afl[mt][0], Afl[mt][1], Afl[mt][2], Afl[mt][3], baseAl + mt * 2048 + aoff);
            }
            uint32_t Bfh[2][4], Bfl[2][4];
#pragma unroll
            for (int hf = 0; hf < 2; ++hf) {
                LDSM4(Bfh[hf][0], Bfh[hf][1], Bfh[hf][2], Bfh[hf][3], baseBh + hf * 2048 + boff);
                LDSM4(Bfl[hf][0], Bfl[hf][1], Bfl[hf][2], Bfl[hf][3], baseBl + hf * 2048 + boff);
            }
#pragma unroll
            for (int mt = 0; mt < 4; ++mt)
#pragma unroll
                for (int nt = 0; nt < 4; ++nt) {
                    const int hf = nt >> 1, od = nt & 1;
                    mma_bf16(acc[mt][nt], Afh[mt], Bfh[hf][od * 2], Bfh[hf][od * 2 + 1]);
                    mma_bf16(acc[mt][nt], Afh[mt], Bfl[hf][od * 2], Bfl[hf][od * 2 + 1]);
                    mma_bf16(acc[mt][nt], Afl[mt], Bfh[hf][od * 2], Bfh[hf][od * 2 + 1]);
                }
        }
        __syncthreads();
    }

    // epilogue: c0,c1 at (row, 2ci), c2,c3 at (row+8, 2ci)
    const int gi = lane >> 2;
    const int ci = lane & 3;
#pragma unroll
    for (int mt = 0; mt < 4; ++mt) {
        const long row  = bm + wm + mt * 16 + gi;
        const long row2 = row + 8;
#pragma unroll
        for (int nt = 0; nt < 4; ++nt) {
            const long col = bn + wn + nt * 8 + ci * 2;
            float v[4] = {acc[mt][nt][0], acc[mt][nt][1], acc[mt][nt][2], acc[mt][nt][3]};
            if (EPI == 1) {
                const float b0 = bias[col], b1 = bias[col + 1];
                v[0] = fmaxf(v[0] + b0, 0.f); v[1] = fmaxf(v[1] + b1, 0.f);
                v[2] = fmaxf(v[2] + b0, 0.f); v[3] = fmaxf(v[3] + b1, 0.f);
            } else if (EPI == 2) {
                const float2 e0 = *(const float2*)(extra + row * N + col);
                const float2 e1 = *(const float2*)(extra + row2 * N + col);
                v[0] += e0.x; v[1] += e0.y; v[2] += e1.x; v[3] += e1.y;
            } else if (EPI == 3) {
                const float2 g0 = *(const float2*)(extra + row * N + col);
                const float2 g1 = *(const float2*)(extra + row2 * N + col);
                v[0] *= g0.x / (1.f + __expf(-g0.x));
                v[1] *= g0.y / (1.f + __expf(-g0.y));
                v[2] *= g1.x / (1.f + __expf(-g1.x));
                v[3] *= g1.y / (1.f + __expf(-g1.y));
            }
            if (OUT == 0) {
                float2 o0 = {v[0], v[1]}, o1 = {v[2], v[3]};
                *(float2*)(C + row * N + col)  = o0;
                *(float2*)(C + row2 * N + col) = o1;
            } else {
                bf16 h0, h1, h2, h3, l0, l1, l2, l3;
                split2(v[0], h0, l0); split2(v[1], h1, l1);
                split2(v[2], h2, l2); split2(v[3], h3, l3);
                *(uint32_t*)(Ch + row * N + col)  = pack_bf2(h0, h1);
                *(uint32_t*)(Cl + row * N + col)  = pack_bf2(l0, l1);
                *(uint32_t*)(Ch + row2 * N + col) = pack_bf2(h2, h3);
                *(uint32_t*)(Cl + row2 * N + col) = pack_bf2(l2, l3);
            }
        }
    }
}

// ---------------- RoPE in-place on q(4 slots)+k(1 slot) of qkv ----------------
__global__ __launch_bounds__(256) void rope_kernel(float* __restrict__ qkv,
                                                   const float* __restrict__ cosb,
                                                   const float* __restrict__ sinb) {
    const int idx = blockIdx.x * 256 + threadIdx.x;
    const int d = idx & 63;
    int vec = idx >> 6;
    const int s = vec % 5; vec /= 5;
    const int g = vec & 7;
    const int t = vec >> 3;
    const long base = (long)t * QKV_N + g * 768 + s * 128;
    const float x1 = qkv[base + d];
    const float x2 = qkv[base + d + 64];
    const float c1 = cosb[t * 128 + d], s1 = sinb[t * 128 + d];
    const float c2 = cosb[t * 128 + d + 64], s2 = sinb[t * 128 + d + 64];
    qkv[base + d]      = x1 * c1 - x2 * s1;
    qkv[base + d + 64] = x2 * c2 + x1 * s2;
}

// ---------------- scale_t[h][t] = mean_d scaling[t][h*128+d] ----------------
__global__ __launch_bounds__(256) void scale_mean_kernel(const float* __restrict__ scaling,
                                                         float* __restrict__ scale_t) {
    const int wid = (blockIdx.x * 256 + threadIdx.x) >> 5;
    const int lane = threadIdx.x & 31;
    const int t = wid >> 5;
    const int h = wid & 31;
    const float4 v = *(const float4*)(scaling + (long)t * C_EMB + h * 128 + lane * 4);
    float s = v.x + v.y + v.z + v.w;
#pragma unroll
    for (int o = 16; o; o >>= 1) s += __shfl_xor_sync(0xffffffffu, s, o);
    if (lane == 0) scale_t[h * T_SEQ + t] = s * (1.f / 128.f);
}

// ---------------- flash attention (non-causal), BQ=64, BK=64, split-bf16 output ----------------
#define FLASH_SMEM_FLOATS (3 * 64 * 128 + 64 * 65 + 3 * 64)
#define FLASH_SMEM_BYTES (FLASH_SMEM_FLOATS * 4)

__device__ __forceinline__ int swz(int row, int dv) {
    return row * 128 + ((dv ^ ((row >> 2) & 7)) << 2);
}

__global__ __launch_bounds__(256, 1)
void flash_kernel(const float* __restrict__ qkv, const float* __restrict__ scale_t,
                  bf16* __restrict__ yh, bf16* __restrict__ yl) {
    extern __shared__ float smf[];
    float* Sq = smf;
    float* Sk = Sq + 64 * 128;
    float* Sv = Sk + 64 * 128;
    float* S  = Sv + 64 * 128;
    float* m_s = S + 64 * 65;
    float* l_s = m_s + 64;
    float* c_s = l_s + 64;

    const int tid = threadIdx.x;
    const int qb = blockIdx.x;
    const int h = blockIdx.y;
    const int g = h >> 2, s = h & 3;
    const float sf = 0.08838834764831845f;

#pragma unroll
    for (int it = 0; it < 8; ++it) {
        const int f = tid + it * 256;
        const int qi = f >> 5;
        const int dv = f & 31;
        const int t = qb * 64 + qi;
        const float sc = sf * scale_t[h * T_SEQ + t];
        float4 v = *(const float4*)(qkv + (long)t * QKV_N + g * 768 + s * 128 + dv * 4);
        v.x *= sc; v.y *= sc; v.z *= sc; v.w *= sc;
        *(float4*)(Sq + qi * 128 + dv * 4) = v;
    }
    if (tid < 64) { m_s[tid] = -1e30f; l_s[tid] = 0.f; }

    float acc[4][8];
#pragma unroll
    for (int i = 0; i < 4; i++)
#pragma unroll
        for (int j = 0; j < 8; j++) acc[i][j] = 0.f;

    const int r0 = (tid & 15) * 4;
    const int c0 = (tid >> 4) * 8;
    const int q0 = (tid >> 4) * 4;
    const int k0 = (tid & 15) * 4;
    __syncthreads();

    for (int kt = 0; kt < 32; ++kt) {
#pragma unroll
        for (int it = 0; it < 8; ++it) {
            const int f = tid + it * 256;
            const int kj = f >> 5;
            const int dv = f & 31;
            const long base = (long)(kt * 64 + kj) * QKV_N + g * 768;
            *(float4*)(Sk + swz(kj, dv)) = *(const float4*)(qkv + base + 4 * 128 + dv * 4);
            *(float4*)(Sv + swz(kj, dv)) = *(const float4*)(qkv + base + 5 * 128 + dv * 4);
        }
        __syncthreads();

        float sacc[4][4];
#pragma unroll
        for (int i = 0; i < 4; i++)
#pragma unroll
            for (int j = 0; j < 4; j++) sacc[i][j] = 0.f;
        for (int d = 0; d < 128; d += 4) {
            float4 a[4], b[4];
#pragma unroll
            for (int i = 0; i < 4; i++) a[i] = *(const float4*)(Sq + (q0 + i) * 128 + d);
#pragma unroll
            for (int j = 0; j < 4; j++) b[j] = *(const float4*)(Sk + swz(k0 + j, d >> 2));
#pragma unroll
            for (int i = 0; i < 4; i++)
#pragma unroll
                for (int j = 0; j < 4; j++)
                    sacc[i][j] += a[i].x * b[j].x + a[i].y * b[j].y + a[i].z * b[j].z + a[i].w * b[j].w;
        }
#pragma unroll
        for (int i = 0; i < 4; i++)
#pragma unroll
            for (int j = 0; j < 4; j++) S[(q0 + i) * 65 + k0 + j] = sacc[i][j];
        __syncthreads();

        {
            const int r = tid >> 2, qd = tid & 3;
            float* row = S + r * 65;
            float tmax = -1e30f;
            for (int j = qd * 16; j < qd * 16 + 16; j++) tmax = fmaxf(tmax, row[j]);
            tmax = fmaxf(tmax, __shfl_xor_sync(0xffffffffu, tmax, 1));
            tmax = fmaxf(tmax, __shfl_xor_sync(0xffffffffu, tmax, 2));
            const float m_old = m_s[r];
            const float m_new = fmaxf(m_old, tmax);
            float psum = 0.f;
            for (int j = qd * 16; j < qd * 16 + 16; j++) {
                const float p = __expf(row[j] - m_new);
                row[j] = p;
                psum += p;
            }
            psum += __shfl_xor_sync(0xffffffffu, psum, 1);
            psum += __shfl_xor_sync(0xffffffffu, psum, 2);
            if (qd == 0) {
                const float corr = __expf(m_old - m_new);
                l_s[r] = l_s[r] * corr + psum;
                m_s[r] = m_new;
                c_s[r] = corr;
            }
        }
        __syncthreads();

        float cr[4];
#pragma unroll
        for (int i = 0; i < 4; i++) cr[i] = c_s[r0 + i];
#pragma unroll
        for (int i = 0; i < 4; i++)
#pragma unroll
            for (int j = 0; j < 8; j++) acc[i][j] *= cr[i];
        for (int kj = 0; kj < 64; ++kj) {
            float p[4];
#pragma unroll
            for (int i = 0; i < 4; i++) p[i] = S[(r0 + i) * 65 + kj];
            const float4 v0 = *(const float4*)(Sv + swz(kj, c0 >> 2));
            const float4 v1 = *(const float4*)(Sv + swz(kj, (c0 >> 2) + 1));
#pragma unroll
            for (int i = 0; i < 4; i++) {
                acc[i][0] += p[i] * v0.x; acc[i][1] += p[i] * v0.y;
                acc[i][2] += p[i] * v0.z; acc[i][3] += p[i] * v0.w;
                acc[i][4] += p[i] * v1.x; acc[i][5] += p[i] * v1.y;
                acc[i][6] += p[i] * v1.z; acc[i][7] += p[i] * v1.w;
            }
        }
        __syncthreads();
    }

#pragma unroll
    for (int i = 0; i < 4; i++) {
        const int t = qb * 64 + r0 + i;
        const float inv_l = 1.f / l_s[r0 + i];
        bf16 hh[8], ll[8];
#pragma unroll
        for (int j = 0; j < 8; j++) split2(acc[i][j] * inv_l, hh[j], ll[j]);
        const long off = (long)t * C_EMB + h * 128 + c0;
        uint4 ho = {pack_bf2(hh[0], hh[1]), pack_bf2(hh[2], hh[3]),
                    pack_bf2(hh[4], hh[5]), pack_bf2(hh[6], hh[7])};
        uint4 lo = {pack_bf2(ll[0], ll[1]), pack_bf2(ll[2], ll[3]),
                    pack_bf2(ll[4], ll[5]), pack_bf2(ll[6], ll[7])};
        *(uint4*)(yh + off) = ho;
        *(uint4*)(yl + off) = lo;
    }
}

// ---------------- host launcher ----------------
extern "C" void kernel_launch(void* const* d_in, const int* in_sizes, int n_in,
                              void* d_out, int out_size) {
    const float* x       = (const float*)d_in[0];
    const float* cosb    = (const float*)d_in[1];
    const float* sinb    = (const float*)d_in[2];
    const float* norm1_w = (const float*)d_in[3];
    const float* norm2_w = (const float*)d_in[4];
    const float* attn_w  = (const float*)d_in[5];
    const float* proj_w  = (const float*)d_in[6];
    const float* scale_w = (const float*)d_in[7];
    const float* scale_b = (const float*)d_in[8];
    const float* gate_w  = (const float*)d_in[9];
    const float* up_w    = (const float*)d_in[10];
    const float* down_w  = (const float*)d_in[11];
    float* out = (float*)d_out;

    float *qkv, *scaling, *scale_t, *resid, *gate;
    cudaGetSymbolAddress((void**)&qkv, g_qkv);
    cudaGetSymbolAddress((void**)&scaling, g_scaling);
    cudaGetSymbolAddress((void**)&scale_t, g_scale_t);
    cudaGetSymbolAddress((void**)&resid, g_resid);
    cudaGetSymbolAddress((void**)&gate, g_gate);

    bf16 *wq_h, *wq_l, *ws_h, *ws_l, *wp_h, *wp_l, *wg_h, *wg_l, *wu_h, *wu_l, *wd_h, *wd_l;
    bf16 *n1_h, *n1_l, *n2_h, *n2_l, *y_h, *y_l, *hb_h, *hb_l;
    cudaGetSymbolAddress((void**)&wq_h, g_wq_h); cudaGetSymbolAddress((void**)&wq_l, g_wq_l);
    cudaGetSymbolAddress((void**)&ws_h, g_ws_h); cudaGetSymbolAddress((void**)&ws_l, g_ws_l);
    cudaGetSymbolAddress((void**)&wp_h, g_wp_h); cudaGetSymbolAddress((void**)&wp_l, g_wp_l);
    cudaGetSymbolAddress((void**)&wg_h, g_wg_h); cudaGetSymbolAddress((void**)&wg_l, g_wg_l);
    cudaGetSymbolAddress((void**)&wu_h, g_wu_h); cudaGetSymbolAddress((void**)&wu_l, g_wu_l);
    cudaGetSymbolAddress((void**)&wd_h, g_wd_h); cudaGetSymbolAddress((void**)&wd_l, g_wd_l);
    cudaGetSymbolAddress((void**)&n1_h, g_n1_h); cudaGetSymbolAddress((void**)&n1_l, g_n1_l);
    cudaGetSymbolAddress((void**)&n2_h, g_n2_h); cudaGetSymbolAddress((void**)&n2_l, g_n2_l);
    cudaGetSymbolAddress((void**)&y_h, g_y_h);   cudaGetSymbolAddress((void**)&y_l, g_y_l);
    cudaGetSymbolAddress((void**)&hb_h, g_hb_h); cudaGetSymbolAddress((void**)&hb_l, g_hb_l);

    cudaFuncSetAttribute(flash_kernel, cudaFuncAttributeMaxDynamicSharedMemorySize, FLASH_SMEM_BYTES);
    cudaFuncSetAttribute(tc_gemm<0, 0>, cudaFuncAttributeMaxDynamicSharedMemorySize, GEMM_SMEM);
    cudaFuncSetAttribute(tc_gemm<1, 0>, cudaFuncAttributeMaxDynamicSharedMemorySize, GEMM_SMEM);
    cudaFuncSetAttribute(tc_gemm<2, 0>, cudaFuncAttributeMaxDynamicSharedMemorySize, GEMM_SMEM);
    cudaFuncSetAttribute(tc_gemm<3, 1>, cudaFuncAttributeMaxDynamicSharedMemorySize, GEMM_SMEM);

    // weight splits (fp32 -> hi/lo bf16 planes)
    split_kernel<<<(QKV_N * C_EMB) / 1024, 256>>>(attn_w, wq_h, wq_l);
    split_kernel<<<(C_EMB * C_EMB) / 1024, 256>>>(scale_w, ws_h, ws_l);
    split_kernel<<<(C_EMB * C_EMB) / 1024, 256>>>(proj_w, wp_h, wp_l);
    split_kernel<<<(FFN_N * C_EMB) / 1024, 256>>>(gate_w, wg_h, wg_l);
    split_kernel<<<(FFN_N * C_EMB) / 1024, 256>>>(up_w, wu_h, wu_l);
    split_kernel<<<(C_EMB * FFN_N) / 1024, 256>>>(down_w, wd_h, wd_l);

    // n1 = rmsnorm(x, norm1_w) -> split planes
    rmsnorm_split<<<T_SEQ, 256>>>(x, norm1_w, n1_h, n1_l);
    // qkv = n1 @ attn_w^T (fp32 out)
    tc_gemm<0, 0><<<dim3(QKV_N / 128, T_SEQ / 128), 256, GEMM_SMEM>>>(
        n1_h, n1_l, wq_h, wq_l, qkv, nullptr, nullptr, T_SEQ, QKV_N, C_EMB, nullptr, nullptr);
    // scaling = relu(n1 @ scale_w^T + b)
    tc_gemm<1, 0><<<dim3(C_EMB / 128, T_SEQ / 128), 256, GEMM_SMEM>>>(
        n1_h, n1_l, ws_h, ws_l, scaling, nullptr, nullptr, T_SEQ, C_EMB, C_EMB, nullptr, scale_b);
    // rope in-place
    rope_kernel<<<(T_SEQ * 8 * 5 * 64) / 256, 256>>>(qkv, cosb, sinb);
    // per-head score scale
    scale_mean_kernel<<<(T_SEQ * N_HEAD_) / 8, 256>>>(scaling, scale_t);
    // flash attention -> y split planes
    flash_kernel<<<dim3(T_SEQ / 64, N_HEAD_), 256, FLASH_SMEM_BYTES>>>(qkv, scale_t, y_h, y_l);
    // resid = x + y @ proj_w^T (fp32)
    tc_gemm<2, 0><<<dim3(C_EMB / 128, T_SEQ / 128), 256, GEMM_SMEM>>>(
        y_h, y_l, wp_h, wp_l, resid, nullptr, nullptr, T_SEQ, C_EMB, C_EMB, x, nullptr);
    // n2 = rmsnorm(resid) -> split planes
    rmsnorm_split<<<T_SEQ, 256>>>(resid, norm2_w, n2_h, n2_l);
    // gate = n2 @ gate_w^T (fp32)
    tc_gemm<0, 0><<<dim3(FFN_N / 128, T_SEQ / 128), 256, GEMM_SMEM>>>(
        n2_h, n2_l, wg_h, wg_l, gate, nullptr, nullptr, T_SEQ, FFN_N, C_EMB, nullptr, nullptr);
    // hbuf = silu(gate) * (n2 @ up_w^T) -> split planes
    tc_gemm<3, 1><<<dim3(FFN_N / 128, T_SEQ / 128), 256, GEMM_SMEM>>>(
        n2_h, n2_l, wu_h, wu_l, nullptr, hb_h, hb_l, T_SEQ, FFN_N, C_EMB, gate, nullptr);
    // out = resid + hbuf @ down_w^T (fp32)
    tc_gemm<2, 0><<<dim3(C_EMB / 128, T_SEQ / 128), 256, GEMM_SMEM>>>(
        hb_h, hb_l, wd_h, wd_l, out, nullptr, nullptr, T_SEQ, C_EMB, FFN_N, resid, nullptr);
}

// round 8
// speedup vs baseline: 1.9634x; 1.9634x over previous
#include <cuda_runtime.h>
#include <cuda_fp16.h>
#include <cstdint>
#include <math.h>

#define T_SEQ   2048
#define C_EMB   4096
#define QKV_N   6144
#define FFN_N   11008
#define N_HEAD_ 32

// ---------------- scratch (static device globals; allocation-free) ----------------
__device__ float g_qkv[T_SEQ * QKV_N];
__device__ float g_scaling[T_SEQ * C_EMB];
__device__ float g_scale_t[N_HEAD_ * T_SEQ];
__device__ float g_resid[T_SEQ * C_EMB];
__device__ float g_gate[T_SEQ * FFN_N];

// fp16 operand planes
__device__ __half g_wq[QKV_N * C_EMB];
__device__ __half g_ws[C_EMB * C_EMB];
__device__ __half g_wp[C_EMB * C_EMB];
__device__ __half g_wg[FFN_N * C_EMB];
__device__ __half g_wu[FFN_N * C_EMB];
__device__ __half g_wd[C_EMB * FFN_N];
__device__ __half g_n1[T_SEQ * C_EMB];
__device__ __half g_n2[T_SEQ * C_EMB];
__device__ __half g_y[T_SEQ * C_EMB];
__device__ __half g_hb[T_SEQ * FFN_N];

// ---------------- small helpers ----------------
__device__ __forceinline__ uint32_t smem_u32(const void* p) {
    return (uint32_t)__cvta_generic_to_shared(p);
}
__device__ __forceinline__ uint32_t pack_h2(__half a, __half b) {
    __half2 p; p.x = a; p.y = b;
    return *(uint32_t*)&p;
}
__device__ __forceinline__ void cp_async16(void* smem_ptr, const void* gptr) {
    unsigned s = (unsigned)__cvta_generic_to_shared(smem_ptr);
    asm volatile("cp.async.cg.shared.global [%0], [%1], 16;" :: "r"(s), "l"(gptr));
}
#define CP_COMMIT() asm volatile("cp.async.commit_group;" ::: "memory")

#define LDSM4(r0, r1, r2, r3, addr) \
    asm volatile("ldmatrix.sync.aligned.m8n8.x4.shared.b16 {%0,%1,%2,%3}, [%4];" \
        : "=r"(r0), "=r"(r1), "=r"(r2), "=r"(r3) : "r"(addr))

__device__ __forceinline__ void mma_fp16(float* d, const uint32_t* a, uint32_t b0, uint32_t b1) {
    asm volatile(
        "mma.sync.aligned.m16n8k16.row.col.f32.f16.f16.f32 "
        "{%0,%1,%2,%3},{%4,%5,%6,%7},{%8,%9},{%0,%1,%2,%3};"
        : "+f"(d[0]), "+f"(d[1]), "+f"(d[2]), "+f"(d[3])
        : "r"(a[0]), "r"(a[1]), "r"(a[2]), "r"(a[3]), "r"(b0), "r"(b1));
}

// ---------------- fp32 -> fp16 convert kernel ----------------
__global__ __launch_bounds__(256) void cvt_kernel(const float* __restrict__ in,
                                                  __half* __restrict__ outp) {
    const long i = ((long)blockIdx.x * 256 + threadIdx.x) * 4;
    const float4 v = *(const float4*)(in + i);
    uint2 o = {pack_h2(__float2half_rn(v.x), __float2half_rn(v.y)),
               pack_h2(__float2half_rn(v.z), __float2half_rn(v.w))};
    *(uint2*)(outp + i) = o;
}

// ---------------- RMSNorm (fp32 in -> fp16 out) ----------------
__global__ __launch_bounds__(256) void rmsnorm_h(const float* __restrict__ x,
                                                 const float* __restrict__ w,
                                                 __half* __restrict__ o) {
    const long row = blockIdx.x;
    const float* xr = x + row * C_EMB;
    const int tid = threadIdx.x;

    float4 v[4];
    float ss = 0.f;
#pragma unroll
    for (int i = 0; i < 4; i++) {
        v[i] = *(const float4*)(xr + tid * 4 + i * 1024);
        ss += v[i].x * v[i].x + v[i].y * v[i].y + v[i].z * v[i].z + v[i].w * v[i].w;
    }
#pragma unroll
    for (int off = 16; off; off >>= 1) ss += __shfl_xor_sync(0xffffffffu, ss, off);
    __shared__ float red[8];
    if ((tid & 31) == 0) red[tid >> 5] = ss;
    __syncthreads();
    float tot = red[0] + red[1] + red[2] + red[3] + red[4] + red[5] + red[6] + red[7];
    const float inv = rsqrtf(tot * (1.f / 4096.f) + 1e-5f);
#pragma unroll
    for (int i = 0; i < 4; i++) {
        float4 wv = *(const float4*)(w + tid * 4 + i * 1024);
        const long off = row * C_EMB + tid * 4 + i * 1024;
        uint2 ou = {pack_h2(__float2half_rn(v[i].x * inv * wv.x), __float2half_rn(v[i].y * inv * wv.y)),
                    pack_h2(__float2half_rn(v[i].z * inv * wv.z), __float2half_rn(v[i].w * inv * wv.w))};
        *(uint2*)(o + off) = ou;
    }
}

// ---------------- fp16 mma GEMM: C[M,N] = A[M,K] * W[N,K]^T ----------------
// Tile 128x128, BK=64, 3-stage cp.async ring, 8 warps (2M x 4N), 64x32 per warp.
// EPI: 0 none, 1 relu(+bias), 2 +extra, 3 silu(extra)*acc.  OUT: 0 fp32 C, 1 fp16 Chalf.
#define STAGE_BYTES 32768   // 2 tiles (A,B) * 128 rows * 128B
#define GEMM_SMEM (3 * STAGE_BYTES)

__device__ __forceinline__ void stage_tiles(char* sm, int stg,
        const __half* __restrict__ A, const __half* __restrict__ B,
        long bm, long bn, long K, int k0, int tid) {
    const int row = tid >> 1;
    const int cb = (tid & 1) * 4;
    char* st = sm + stg * STAGE_BYTES;
    const char* srcA = (const char*)(A + (bm + row) * K + k0);
    const char* srcB = (const char*)(B + (bn + row) * K + k0);
#pragma unroll
    for (int c = 0; c < 4; c++) {
        const int chunk = cb + c;
        const int sw = row * 128 + ((chunk ^ (row & 7)) << 4);
        cp_async16(st + sw, srcA + chunk * 16);
        cp_async16(st + 16384 + sw, srcB + chunk * 16);
    }
}

template <int EPI, int OUT>
__global__ __launch_bounds__(256, 2)
void hgemm(const __half* __restrict__ A, const __half* __restrict__ B,
           float* __restrict__ C, __half* __restrict__ Chalf,
           int M, int N, int K,
           const float* __restrict__ extra, const float* __restrict__ bias) {
    extern __shared__ __align__(1024) char sm[];
    const uint32_t sbase = smem_u32(sm);

    const int tid  = threadIdx.x;
    const int warp = tid >> 5;
    const int lane = tid & 31;
    const long bm = (long)blockIdx.y * 128;
    const long bn = (long)blockIdx.x * 128;
    const int wm = (warp & 1) * 64;
    const int wn = (warp >> 1) * 32;

    const int ar = (lane & 7) + ((lane >> 3) & 1) * 8;
    const int ac = lane >> 4;
    const int br = (lane & 7) + ((lane >> 4) & 1) * 8;
    const int bc = (lane >> 3) & 1;
    const int xr = lane & 7;

    float acc[4][4][4];
#pragma unroll
    for (int mt = 0; mt < 4; mt++)
#pragma unroll
        for (int nt = 0; nt < 4; nt++)
#pragma unroll
            for (int u = 0; u < 4; u++) acc[mt][nt][u] = 0.f;

    const int steps = K >> 6;
    stage_tiles(sm, 0, A, B, bm, bn, K, 0, tid);  CP_COMMIT();
    stage_tiles(sm, 1, A, B, bm, bn, K, 64, tid); CP_COMMIT();

    for (int s = 0; s < steps; ++s) {
        const int buf = s % 3;
        if (s + 1 < steps) { asm volatile("cp.async.wait_group 1;" ::: "memory"); }
        else               { asm volatile("cp.async.wait_group 0;" ::: "memory"); }
        __syncthreads();
        if (s + 2 < steps) {
            stage_tiles(sm, (s + 2) % 3, A, B, bm, bn, K, (s + 2) * 64, tid);
            CP_COMMIT();
        }
        const uint32_t st = sbase + buf * STAGE_BYTES;
        const uint32_t baseA = st + (wm + ar) * 128;
        const uint32_t baseB = st + 16384 + (wn + br) * 128;

#pragma unroll
        for (int kc = 0; kc < 4; ++kc) {
            const uint32_t aoff = ((((kc << 1) + ac) ^ xr) << 4);
            const uint32_t boff = ((((kc << 1) + bc) ^ xr) << 4);
            uint32_t Af[4][4];
#pragma unroll
            for (int mt = 0; mt < 4; ++mt)
                LDSM4(Af[mt][0], Af[mt][1], Af[mt][2], Af[mt][3], baseA + mt * 2048 + aoff);
            uint32_t Bf[2][4];
#pragma unroll
            for (int hf = 0; hf < 2; ++hf)
                LDSM4(Bf[hf][0], Bf[hf][1], Bf[hf][2], Bf[hf][3], baseB + hf * 2048 + boff);
#pragma unroll
            for (int mt = 0; mt < 4; ++mt)
#pragma unroll
                for (int nt = 0; nt < 4; ++nt) {
                    const int hf = nt >> 1, od = nt & 1;
                    mma_fp16(acc[mt][nt], Af[mt], Bf[hf][od * 2], Bf[hf][od * 2 + 1]);
                }
        }
        __syncthreads();
    }

    const int gi = lane >> 2;
    const int ci = lane & 3;
#pragma unroll
    for (int mt = 0; mt < 4; ++mt) {
        const long row  = bm + wm + mt * 16 + gi;
        const long row2 = row + 8;
#pragma unroll
        for (int nt = 0; nt < 4; ++nt) {
            const long col = bn + wn + nt * 8 + ci * 2;
            float v[4] = {acc[mt][nt][0], acc[mt][nt][1], acc[mt][nt][2], acc[mt][nt][3]};
            if (EPI == 1) {
                const float b0 = bias[col], b1 = bias[col + 1];
                v[0] = fmaxf(v[0] + b0, 0.f); v[1] = fmaxf(v[1] + b1, 0.f);
                v[2] = fmaxf(v[2] + b0, 0.f); v[3] = fmaxf(v[3] + b1, 0.f);
            } else if (EPI == 2) {
                const float2 e0 = *(const float2*)(extra + row * N + col);
                const float2 e1 = *(const float2*)(extra + row2 * N + col);
                v[0] += e0.x; v[1] += e0.y; v[2] += e1.x; v[3] += e1.y;
            } else if (EPI == 3) {
                const float2 g0 = *(const float2*)(extra + row * N + col);
                const float2 g1 = *(const float2*)(extra + row2 * N + col);
                v[0] *= g0.x / (1.f + __expf(-g0.x));
                v[1] *= g0.y / (1.f + __expf(-g0.y));
                v[2] *= g1.x / (1.f + __expf(-g1.x));
                v[3] *= g1.y / (1.f + __expf(-g1.y));
            }
            if (OUT == 0) {
                float2 o0 = {v[0], v[1]}, o1 = {v[2], v[3]};
                *(float2*)(C + row * N + col)  = o0;
                *(float2*)(C + row2 * N + col) = o1;
            } else {
                *(uint32_t*)(Chalf + row * N + col)  = pack_h2(__float2half_rn(v[0]), __float2half_rn(v[1]));
                *(uint32_t*)(Chalf + row2 * N + col) = pack_h2(__float2half_rn(v[2]), __float2half_rn(v[3]));
            }
        }
    }
}

// ---------------- RoPE in-place on q(4 slots)+k(1 slot) of qkv ----------------
__global__ __launch_bounds__(256) void rope_kernel(float* __restrict__ qkv,
                                                   const float* __restrict__ cosb,
                                                   const float* __restrict__ sinb) {
    const int idx = blockIdx.x * 256 + threadIdx.x;
    const int d = idx & 63;
    int vec = idx >> 6;
    const int s = vec % 5; vec /= 5;
    const int g = vec & 7;
    const int t = vec >> 3;
    const long base = (long)t * QKV_N + g * 768 + s * 128;
    const float x1 = qkv[base + d];
    const float x2 = qkv[base + d + 64];
    const float c1 = cosb[t * 128 + d], s1 = sinb[t * 128 + d];
    const float c2 = cosb[t * 128 + d + 64], s2 = sinb[t * 128 + d + 64];
    qkv[base + d]      = x1 * c1 - x2 * s1;
    qkv[base + d + 64] = x2 * c2 + x1 * s2;
}

// ---------------- scale_t[h][t] = mean_d scaling[t][h*128+d] ----------------
__global__ __launch_bounds__(256) void scale_mean_kernel(const float* __restrict__ scaling,
                                                         float* __restrict__ scale_t) {
    const int wid = (blockIdx.x * 256 + threadIdx.x) >> 5;
    const int lane = threadIdx.x & 31;
    const int t = wid >> 5;
    const int h = wid & 31;
    const float4 v = *(const float4*)(scaling + (long)t * C_EMB + h * 128 + lane * 4);
    float s = v.x + v.y + v.z + v.w;
#pragma unroll
    for (int o = 16; o; o >>= 1) s += __shfl_xor_sync(0xffffffffu, s, o);
    if (lane == 0) scale_t[h * T_SEQ + t] = s * (1.f / 128.f);
}

// ---------------- flash attention (non-causal), BQ=64, BK=64, fp16 output ----------------
#define FLASH_SMEM_FLOATS (3 * 64 * 128 + 64 * 65 + 3 * 64)
#define FLASH_SMEM_BYTES (FLASH_SMEM_FLOATS * 4)

__device__ __forceinline__ int swz(int row, int dv) {
    return row * 128 + ((dv ^ ((row >> 2) & 7)) << 2);
}

__global__ __launch_bounds__(256, 1)
void flash_kernel(const float* __restrict__ qkv, const float* __restrict__ scale_t,
                  __half* __restrict__ y) {
    extern __shared__ float smf[];
    float* Sq = smf;
    float* Sk = Sq + 64 * 128;
    float* Sv = Sk + 64 * 128;
    float* S  = Sv + 64 * 128;
    float* m_s = S + 64 * 65;
    float* l_s = m_s + 64;
    float* c_s = l_s + 64;

    const int tid = threadIdx.x;
    const int qb = blockIdx.x;
    const int h = blockIdx.y;
    const int g = h >> 2, s = h & 3;
    const float sf = 0.08838834764831845f;

#pragma unroll
    for (int it = 0; it < 8; ++it) {
        const int f = tid + it * 256;
        const int qi = f >> 5;
        const int dv = f & 31;
        const int t = qb * 64 + qi;
        const float sc = sf * scale_t[h * T_SEQ + t];
        float4 v = *(const float4*)(qkv + (long)t * QKV_N + g * 768 + s * 128 + dv * 4);
        v.x *= sc; v.y *= sc; v.z *= sc; v.w *= sc;
        *(float4*)(Sq + qi * 128 + dv * 4) = v;
    }
    if (tid < 64) { m_s[tid] = -1e30f; l_s[tid] = 0.f; }

    float acc[4][8];
#pragma unroll
    for (int i = 0; i < 4; i++)
#pragma unroll
        for (int j = 0; j < 8; j++) acc[i][j] = 0.f;

    const int r0 = (tid & 15) * 4;
    const int c0 = (tid >> 4) * 8;
    const int q0 = (tid >> 4) * 4;
    const int k0 = (tid & 15) * 4;
    __syncthreads();

    for (int kt = 0; kt < 32; ++kt) {
#pragma unroll
        for (int it = 0; it < 8; ++it) {
            const int f = tid + it * 256;
            const int kj = f >> 5;
            const int dv = f & 31;
            const long base = (long)(kt * 64 + kj) * QKV_N + g * 768;
            *(float4*)(Sk + swz(kj, dv)) = *(const float4*)(qkv + base + 4 * 128 + dv * 4);
            *(float4*)(Sv + swz(kj, dv)) = *(const float4*)(qkv + base + 5 * 128 + dv * 4);
        }
        __syncthreads();

        float sacc[4][4];
#pragma unroll
        for (int i = 0; i < 4; i++)
#pragma unroll
            for (int j = 0; j < 4; j++) sacc[i][j] = 0.f;
        for (int d = 0; d < 128; d += 4) {
            float4 a[4], b[4];
#pragma unroll
            for (int i = 0; i < 4; i++) a[i] = *(const float4*)(Sq + (q0 + i) * 128 + d);
#pragma unroll
            for (int j = 0; j < 4; j++) b[j] = *(const float4*)(Sk + swz(k0 + j, d >> 2));
#pragma unroll
            for (int i = 0; i < 4; i++)
#pragma unroll
                for (int j = 0; j < 4; j++)
                    sacc[i][j] += a[i].x * b[j].x + a[i].y * b[j].y + a[i].z * b[j].z + a[i].w * b[j].w;
        }
#pragma unroll
        for (int i = 0; i < 4; i++)
#pragma unroll
            for (int j = 0; j < 4; j++) S[(q0 + i) * 65 + k0 + j] = sacc[i][j];
        __syncthreads();

        {
            const int r = tid >> 2, qd = tid & 3;
            float* row = S + r * 65;
            float tmax = -1e30f;
            for (int j = qd * 16; j < qd * 16 + 16; j++) tmax = fmaxf(tmax, row[j]);
            tmax = fmaxf(tmax, __shfl_xor_sync(0xffffffffu, tmax, 1));
            tmax = fmaxf(tmax, __shfl_xor_sync(0xffffffffu, tmax, 2));
            const float m_old = m_s[r];
            const float m_new = fmaxf(m_old, tmax);
            float psum = 0.f;
            for (int j = qd * 16; j < qd * 16 + 16; j++) {
                const float p = __expf(row[j] - m_new);
                row[j] = p;
                psum += p;
            }
            psum += __shfl_xor_sync(0xffffffffu, psum, 1);
            psum += __shfl_xor_sync(0xffffffffu, psum, 2);
            if (qd == 0) {
                const float corr = __expf(m_old - m_new);
                l_s[r] = l_s[r] * corr + psum;
                m_s[r] = m_new;
                c_s[r] = corr;
            }
        }
        __syncthreads();

        float cr[4];
#pragma unroll
        for (int i = 0; i < 4; i++) cr[i] = c_s[r0 + i];
#pragma unroll
        for (int i = 0; i < 4; i++)
#pragma unroll
            for (int j = 0; j < 8; j++) acc[i][j] *= cr[i];
        for (int kj = 0; kj < 64; ++kj) {
            float p[4];
#pragma unroll
            for (int i = 0; i < 4; i++) p[i] = S[(r0 + i) * 65 + kj];
            const float4 v0 = *(const float4*)(Sv + swz(kj, c0 >> 2));
            const float4 v1 = *(const float4*)(Sv + swz(kj, (c0 >> 2) + 1));
#pragma unroll
            for (int i = 0; i < 4; i++) {
                acc[i][0] += p[i] * v0.x; acc[i][1] += p[i] * v0.y;
                acc[i][2] += p[i] * v0.z; acc[i][3] += p[i] * v0.w;
                acc[i][4] += p[i] * v1.x; acc[i][5] += p[i] * v1.y;
                acc[i][6] += p[i] * v1.z; acc[i][7] += p[i] * v1.w;
            }
        }
        __syncthreads();
    }

#pragma unroll
    for (int i = 0; i < 4; i++) {
        const int t = qb * 64 + r0 + i;
        const float inv_l = 1.f / l_s[r0 + i];
        const long off = (long)t * C_EMB + h * 128 + c0;
        uint4 ho = {pack_h2(__float2half_rn(acc[i][0] * inv_l), __float2half_rn(acc[i][1] * inv_l)),
                    pack_h2(__float2half_rn(acc[i][2] * inv_l), __float2half_rn(acc[i][3] * inv_l)),
                    pack_h2(__float2half_rn(acc[i][4] * inv_l), __float2half_rn(acc[i][5] * inv_l)),
                    pack_h2(__float2half_rn(acc[i][6] * inv_l), __float2half_rn(acc[i][7] * inv_l))};
        *(uint4*)(y + off) = ho;
    }
}

// ---------------- host launcher ----------------
extern "C" void kernel_launch(void* const* d_in, const int* in_sizes, int n_in,
                              void* d_out, int out_size) {
    const float* x       = (const float*)d_in[0];
    const float* cosb    = (const float*)d_in[1];
    const float* sinb    = (const float*)d_in[2];
    const float* norm1_w = (const float*)d_in[3];
    const float* norm2_w = (const float*)d_in[4];
    const float* attn_w  = (const float*)d_in[5];
    const float* proj_w  = (const float*)d_in[6];
    const float* scale_w = (const float*)d_in[7];
    const float* scale_b = (const float*)d_in[8];
    const float* gate_w  = (const float*)d_in[9];
    const float* up_w    = (const float*)d_in[10];
    const float* down_w  = (const float*)d_in[11];
    float* out = (float*)d_out;

    float *qkv, *scaling, *scale_t, *resid, *gate;
    cudaGetSymbolAddress((void**)&qkv, g_qkv);
    cudaGetSymbolAddress((void**)&scaling, g_scaling);
    cudaGetSymbolAddress((void**)&scale_t, g_scale_t);
    cudaGetSymbolAddress((void**)&resid, g_resid);
    cudaGetSymbolAddress((void**)&gate, g_gate);

    __half *wq, *ws, *wp, *wg, *wu, *wd, *n1, *n2, *y, *hb;
    cudaGetSymbolAddress((void**)&wq, g_wq);
    cudaGetSymbolAddress((void**)&ws, g_ws);
    cudaGetSymbolAddress((void**)&wp, g_wp);
    cudaGetSymbolAddress((void**)&wg, g_wg);
    cudaGetSymbolAddress((void**)&wu, g_wu);
    cudaGetSymbolAddress((void**)&wd, g_wd);
    cudaGetSymbolAddress((void**)&n1, g_n1);
    cudaGetSymbolAddress((void**)&n2, g_n2);
    cudaGetSymbolAddress((void**)&y, g_y);
    cudaGetSymbolAddress((void**)&hb, g_hb);

    cudaFuncSetAttribute(flash_kernel, cudaFuncAttributeMaxDynamicSharedMemorySize, FLASH_SMEM_BYTES);
    cudaFuncSetAttribute(hgemm<0, 0>, cudaFuncAttributeMaxDynamicSharedMemorySize, GEMM_SMEM);
    cudaFuncSetAttribute(hgemm<1, 0>, cudaFuncAttributeMaxDynamicSharedMemorySize, GEMM_SMEM);
    cudaFuncSetAttribute(hgemm<2, 0>, cudaFuncAttributeMaxDynamicSharedMemorySize, GEMM_SMEM);
    cudaFuncSetAttribute(hgemm<3, 1>, cudaFuncAttributeMaxDynamicSharedMemorySize, GEMM_SMEM);

    // weight converts (fp32 -> fp16)
    cvt_kernel<<<(QKV_N * C_EMB) / 1024, 256>>>(attn_w, wq);
    cvt_kernel<<<(C_EMB * C_EMB) / 1024, 256>>>(scale_w, ws);
    cvt_kernel<<<(C_EMB * C_EMB) / 1024, 256>>>(proj_w, wp);
    cvt_kernel<<<(FFN_N * C_EMB) / 1024, 256>>>(gate_w, wg);
    cvt_kernel<<<(FFN_N * C_EMB) / 1024, 256>>>(up_w, wu);
    cvt_kernel<<<(C_EMB * FFN_N) / 1024, 256>>>(down_w, wd);

    // n1 = rmsnorm(x, norm1_w) -> fp16
    rmsnorm_h<<<T_SEQ, 256>>>(x, norm1_w, n1);
    // qkv = n1 @ attn_w^T (fp32 out)
    hgemm<0, 0><<<dim3(QKV_N / 128, T_SEQ / 128), 256, GEMM_SMEM>>>(
        n1, wq, qkv, nullptr, T_SEQ, QKV_N, C_EMB, nullptr, nullptr);
    // scaling = relu(n1 @ scale_w^T + b) (fp32)
    hgemm<1, 0><<<dim3(C_EMB / 128, T_SEQ / 128), 256, GEMM_SMEM>>>(
        n1, ws, scaling, nullptr, T_SEQ, C_EMB, C_EMB, nullptr, scale_b);
    // rope in-place
    rope_kernel<<<(T_SEQ * 8 * 5 * 64) / 256, 256>>>(qkv, cosb, sinb);
    // per-head score scale
    scale_mean_kernel<<<(T_SEQ * N_HEAD_) / 8, 256>>>(scaling, scale_t);
    // flash attention -> y fp16
    flash_kernel<<<dim3(T_SEQ / 64, N_HEAD_), 256, FLASH_SMEM_BYTES>>>(qkv, scale_t, y);
    // resid = x + y @ proj_w^T (fp32)
    hgemm<2, 0><<<dim3(C_EMB / 128, T_SEQ / 128), 256, GEMM_SMEM>>>(
        y, wp, resid, nullptr, T_SEQ, C_EMB, C_EMB, x, nullptr);
    // n2 = rmsnorm(resid) -> fp16
    rmsnorm_h<<<T_SEQ, 256>>>(resid, norm2_w, n2);
    // gate = n2 @ gate_w^T (fp32)
    hgemm<0, 0><<<dim3(FFN_N / 128, T_SEQ / 128), 256, GEMM_SMEM>>>(
        n2, wg, gate, nullptr, T_SEQ, FFN_N, C_EMB, nullptr, nullptr);
    // hbuf = silu(gate) * (n2 @ up_w^T) -> fp16
    hgemm<3, 1><<<dim3(FFN_N / 128, T_SEQ / 128), 256, GEMM_SMEM>>>(
        n2, wu, nullptr, hb, T_SEQ, FFN_N, C_EMB, gate, nullptr);
    // out = resid + hbuf @ down_w^T (fp32)
    hgemm<2, 0><<<dim3(C_EMB / 128, T_SEQ / 128), 256, GEMM_SMEM>>>(
        hb, wd, out, nullptr, T_SEQ, C_EMB, FFN_N, resid, nullptr);
}

// round 9
// speedup vs baseline: 3.0403x; 1.5485x over previous
#include <cuda_runtime.h>
#include <cuda_fp16.h>
#include <cstdint>
#include <math.h>

#define T_SEQ   2048
#define C_EMB   4096
#define QKV_N   6144
#define FFN_N   11008
#define N_HEAD_ 32

// ---------------- scratch (static device globals; allocation-free) ----------------
__device__ float g_qkv[T_SEQ * QKV_N];
__device__ float g_scaling[T_SEQ * C_EMB];
__device__ float g_scale_t[N_HEAD_ * T_SEQ];
__device__ float g_resid[T_SEQ * C_EMB];
__device__ float g_gate[T_SEQ * FFN_N];

// fp16 operand planes
__device__ __half g_wq[QKV_N * C_EMB];
__device__ __half g_ws[C_EMB * C_EMB];
__device__ __half g_wp[C_EMB * C_EMB];
__device__ __half g_wg[FFN_N * C_EMB];
__device__ __half g_wu[FFN_N * C_EMB];
__device__ __half g_wd[C_EMB * FFN_N];
__device__ __half g_n1[T_SEQ * C_EMB];
__device__ __half g_n2[T_SEQ * C_EMB];
__device__ __half g_y[T_SEQ * C_EMB];
__device__ __half g_hb[T_SEQ * FFN_N];
// fp16 attention operands (roped / scaled)
__device__ __half g_qh[N_HEAD_ * T_SEQ * 128];
__device__ __half g_kh[8 * T_SEQ * 128];
__device__ __half g_vh[8 * T_SEQ * 128];

// ---------------- small helpers ----------------
__device__ __forceinline__ uint32_t smem_u32(const void* p) {
    return (uint32_t)__cvta_generic_to_shared(p);
}
__device__ __forceinline__ uint32_t pack_h2(__half a, __half b) {
    __half2 p; p.x = a; p.y = b;
    return *(uint32_t*)&p;
}
__device__ __forceinline__ uint32_t pack_f2h(float a, float b) {
    return pack_h2(__float2half_rn(a), __float2half_rn(b));
}
__device__ __forceinline__ void cp_async16(void* smem_ptr, const void* gptr) {
    unsigned s = (unsigned)__cvta_generic_to_shared(smem_ptr);
    asm volatile("cp.async.cg.shared.global [%0], [%1], 16;" :: "r"(s), "l"(gptr));
}
#define CP_COMMIT() asm volatile("cp.async.commit_group;" ::: "memory")

#define LDSM4(r0, r1, r2, r3, addr) \
    asm volatile("ldmatrix.sync.aligned.m8n8.x4.shared.b16 {%0,%1,%2,%3}, [%4];" \
        : "=r"(r0), "=r"(r1), "=r"(r2), "=r"(r3) : "r"(addr))
#define LDSM4T(r0, r1, r2, r3, addr) \
    asm volatile("ldmatrix.sync.aligned.m8n8.x4.trans.shared.b16 {%0,%1,%2,%3}, [%4];" \
        : "=r"(r0), "=r"(r1), "=r"(r2), "=r"(r3) : "r"(addr))

__device__ __forceinline__ void mma_fp16(float* d, const uint32_t* a, uint32_t b0, uint32_t b1) {
    asm volatile(
        "mma.sync.aligned.m16n8k16.row.col.f32.f16.f16.f32 "
        "{%0,%1,%2,%3},{%4,%5,%6,%7},{%8,%9},{%0,%1,%2,%3};"
        : "+f"(d[0]), "+f"(d[1]), "+f"(d[2]), "+f"(d[3])
        : "r"(a[0]), "r"(a[1]), "r"(a[2]), "r"(a[3]), "r"(b0), "r"(b1));
}

// ---------------- fp32 -> fp16 convert kernel ----------------
__global__ __launch_bounds__(256) void cvt_kernel(const float* __restrict__ in,
                                                  __half* __restrict__ outp) {
    const long i = ((long)blockIdx.x * 256 + threadIdx.x) * 4;
    const float4 v = *(const float4*)(in + i);
    uint2 o = {pack_f2h(v.x, v.y), pack_f2h(v.z, v.w)};
    *(uint2*)(outp + i) = o;
}

// ---------------- RMSNorm (fp32 in -> fp16 out) ----------------
__global__ __launch_bounds__(256) void rmsnorm_h(const float* __restrict__ x,
                                                 const float* __restrict__ w,
                                                 __half* __restrict__ o) {
    const long row = blockIdx.x;
    const float* xr = x + row * C_EMB;
    const int tid = threadIdx.x;

    float4 v[4];
    float ss = 0.f;
#pragma unroll
    for (int i = 0; i < 4; i++) {
        v[i] = *(const float4*)(xr + tid * 4 + i * 1024);
        ss += v[i].x * v[i].x + v[i].y * v[i].y + v[i].z * v[i].z + v[i].w * v[i].w;
    }
#pragma unroll
    for (int off = 16; off; off >>= 1) ss += __shfl_xor_sync(0xffffffffu, ss, off);
    __shared__ float red[8];
    if ((tid & 31) == 0) red[tid >> 5] = ss;
    __syncthreads();
    float tot = red[0] + red[1] + red[2] + red[3] + red[4] + red[5] + red[6] + red[7];
    const float inv = rsqrtf(tot * (1.f / 4096.f) + 1e-5f);
#pragma unroll
    for (int i = 0; i < 4; i++) {
        float4 wv = *(const float4*)(w + tid * 4 + i * 1024);
        const long off = row * C_EMB + tid * 4 + i * 1024;
        uint2 ou = {pack_f2h(v[i].x * inv * wv.x, v[i].y * inv * wv.y),
                    pack_f2h(v[i].z * inv * wv.z, v[i].w * inv * wv.w)};
        *(uint2*)(o + off) = ou;
    }
}

// ---------------- fp16 mma GEMM: C[M,N] = A[M,K] * W[N,K]^T ----------------
#define STAGE_BYTES 32768
#define GEMM_SMEM (3 * STAGE_BYTES)

__device__ __forceinline__ void stage_tiles(char* sm, int stg,
        const __half* __restrict__ A, const __half* __restrict__ B,
        long bm, long bn, long K, int k0, int tid) {
    const int row = tid >> 1;
    const int cb = (tid & 1) * 4;
    char* st = sm + stg * STAGE_BYTES;
    const char* srcA = (const char*)(A + (bm + row) * K + k0);
    const char* srcB = (const char*)(B + (bn + row) * K + k0);
#pragma unroll
    for (int c = 0; c < 4; c++) {
        const int chunk = cb + c;
        const int sw = row * 128 + ((chunk ^ (row & 7)) << 4);
        cp_async16(st + sw, srcA + chunk * 16);
        cp_async16(st + 16384 + sw, srcB + chunk * 16);
    }
}

template <int EPI, int OUT>
__global__ __launch_bounds__(256, 2)
void hgemm(const __half* __restrict__ A, const __half* __restrict__ B,
           float* __restrict__ C, __half* __restrict__ Chalf,
           int M, int N, int K,
           const float* __restrict__ extra, const float* __restrict__ bias) {
    extern __shared__ __align__(1024) char sm[];
    const uint32_t sbase = smem_u32(sm);

    const int tid  = threadIdx.x;
    const int warp = tid >> 5;
    const int lane = tid & 31;
    const long bm = (long)blockIdx.y * 128;
    const long bn = (long)blockIdx.x * 128;
    const int wm = (warp & 1) * 64;
    const int wn = (warp >> 1) * 32;

    const int ar = (lane & 7) + ((lane >> 3) & 1) * 8;
    const int ac = lane >> 4;
    const int br = (lane & 7) + ((lane >> 4) & 1) * 8;
    const int bc = (lane >> 3) & 1;
    const int xr = lane & 7;

    float acc[4][4][4];
#pragma unroll
    for (int mt = 0; mt < 4; mt++)
#pragma unroll
        for (int nt = 0; nt < 4; nt++)
#pragma unroll
            for (int u = 0; u < 4; u++) acc[mt][nt][u] = 0.f;

    const int steps = K >> 6;
    stage_tiles(sm, 0, A, B, bm, bn, K, 0, tid);  CP_COMMIT();
    stage_tiles(sm, 1, A, B, bm, bn, K, 64, tid); CP_COMMIT();

    for (int s = 0; s < steps; ++s) {
        const int buf = s % 3;
        if (s + 1 < steps) { asm volatile("cp.async.wait_group 1;" ::: "memory"); }
        else               { asm volatile("cp.async.wait_group 0;" ::: "memory"); }
        __syncthreads();
        if (s + 2 < steps) {
            stage_tiles(sm, (s + 2) % 3, A, B, bm, bn, K, (s + 2) * 64, tid);
            CP_COMMIT();
        }
        const uint32_t st = sbase + buf * STAGE_BYTES;
        const uint32_t baseA = st + (wm + ar) * 128;
        const uint32_t baseB = st + 16384 + (wn + br) * 128;

#pragma unroll
        for (int kc = 0; kc < 4; ++kc) {
            const uint32_t aoff = ((((kc << 1) + ac) ^ xr) << 4);
            const uint32_t boff = ((((kc << 1) + bc) ^ xr) << 4);
            uint32_t Af[4][4];
#pragma unroll
            for (int mt = 0; mt < 4; ++mt)
                LDSM4(Af[mt][0], Af[mt][1], Af[mt][2], Af[mt][3], baseA + mt * 2048 + aoff);
            uint32_t Bf[2][4];
#pragma unroll
            for (int hf = 0; hf < 2; ++hf)
                LDSM4(Bf[hf][0], Bf[hf][1], Bf[hf][2], Bf[hf][3], baseB + hf * 2048 + boff);
#pragma unroll
            for (int mt = 0; mt < 4; ++mt)
#pragma unroll
                for (int nt = 0; nt < 4; ++nt) {
                    const int hf = nt >> 1, od = nt & 1;
                    mma_fp16(acc[mt][nt], Af[mt], Bf[hf][od * 2], Bf[hf][od * 2 + 1]);
                }
        }
        __syncthreads();
    }

    const int gi = lane >> 2;
    const int ci = lane & 3;
#pragma unroll
    for (int mt = 0; mt < 4; ++mt) {
        const long row  = bm + wm + mt * 16 + gi;
        const long row2 = row + 8;
#pragma unroll
        for (int nt = 0; nt < 4; ++nt) {
            const long col = bn + wn + nt * 8 + ci * 2;
            float v[4] = {acc[mt][nt][0], acc[mt][nt][1], acc[mt][nt][2], acc[mt][nt][3]};
            if (EPI == 1) {
                const float b0 = bias[col], b1 = bias[col + 1];
                v[0] = fmaxf(v[0] + b0, 0.f); v[1] = fmaxf(v[1] + b1, 0.f);
                v[2] = fmaxf(v[2] + b0, 0.f); v[3] = fmaxf(v[3] + b1, 0.f);
            } else if (EPI == 2) {
                const float2 e0 = *(const float2*)(extra + row * N + col);
                const float2 e1 = *(const float2*)(extra + row2 * N + col);
                v[0] += e0.x; v[1] += e0.y; v[2] += e1.x; v[3] += e1.y;
            } else if (EPI == 3) {
                const float2 g0 = *(const float2*)(extra + row * N + col);
                const float2 g1 = *(const float2*)(extra + row2 * N + col);
                v[0] *= g0.x / (1.f + __expf(-g0.x));
                v[1] *= g0.y / (1.f + __expf(-g0.y));
                v[2] *= g1.x / (1.f + __expf(-g1.x));
                v[3] *= g1.y / (1.f + __expf(-g1.y));
            }
            if (OUT == 0) {
                float2 o0 = {v[0], v[1]}, o1 = {v[2], v[3]};
                *(float2*)(C + row * N + col)  = o0;
                *(float2*)(C + row2 * N + col) = o1;
            } else {
                *(uint32_t*)(Chalf + row * N + col)  = pack_f2h(v[0], v[1]);
                *(uint32_t*)(Chalf + row2 * N + col) = pack_f2h(v[2], v[3]);
            }
        }
    }
}

// ---------------- scale_t[h][t] = mean_d scaling[t][h*128+d] ----------------
__global__ __launch_bounds__(256) void scale_mean_kernel(const float* __restrict__ scaling,
                                                         float* __restrict__ scale_t) {
    const int wid = (blockIdx.x * 256 + threadIdx.x) >> 5;
    const int lane = threadIdx.x & 31;
    const int t = wid >> 5;
    const int h = wid & 31;
    const float4 v = *(const float4*)(scaling + (long)t * C_EMB + h * 128 + lane * 4);
    float s = v.x + v.y + v.z + v.w;
#pragma unroll
    for (int o = 16; o; o >>= 1) s += __shfl_xor_sync(0xffffffffu, s, o);
    if (lane == 0) scale_t[h * T_SEQ + t] = s * (1.f / 128.f);
}

// ---------------- qkv_prep: rope + q prescale + fp32->fp16 into Q/K/V planes ----------------
__global__ __launch_bounds__(128) void qkv_prep(const float* __restrict__ qkv,
                                                const float* __restrict__ cosb,
                                                const float* __restrict__ sinb,
                                                const float* __restrict__ scale_t,
                                                __half* __restrict__ qh,
                                                __half* __restrict__ kh,
                                                __half* __restrict__ vh) {
    const int t = blockIdx.x;
    const int g = blockIdx.y;
    const int d = threadIdx.x;
    const float c = cosb[t * 128 + d];
    const float s = sinb[t * 128 + d];
    const float sf = 0.08838834764831845f;
    const float* base = qkv + (long)t * QKV_N + g * 768;

#pragma unroll
    for (int slot = 0; slot < 4; ++slot) {
        const float* p = base + slot * 128;
        const float xd = p[d];
        const float xo = p[d ^ 64];
        const float rot = (d < 64) ? -xo : xo;
        const int h = g * 4 + slot;
        const float q = (xd * c + rot * s) * sf * scale_t[h * T_SEQ + t];
        qh[((long)h * T_SEQ + t) * 128 + d] = __float2half_rn(q);
    }
    {
        const float* p = base + 4 * 128;
        const float xd = p[d];
        const float xo = p[d ^ 64];
        const float rot = (d < 64) ? -xo : xo;
        kh[((long)g * T_SEQ + t) * 128 + d] = __float2half_rn(xd * c + rot * s);
    }
    vh[((long)g * T_SEQ + t) * 128 + d] = __float2half_rn(base[5 * 128 + d]);
}

// ---------------- flash attention on fp16 mma (FA2-style, non-causal) ----------------
// CTA: 128 Q rows x 1 head. 8 warps x 16 rows. KV tiles of 64, 2-stage cp.async ring.
// smem: Qs 32KB | stage0 (K 16KB, V 16KB) | stage1 (K 16KB, V 16KB) = 96KB
#define FL_QS     0
#define FL_STAGE0 32768
#define FL_STAGEB 32768
#define FLASH_SMEM (32768 + 2 * 32768)

__global__ __launch_bounds__(256, 1)
void flash_mma(const __half* __restrict__ qh, const __half* __restrict__ kh,
               const __half* __restrict__ vh, __half* __restrict__ y) {
    extern __shared__ __align__(1024) char sm[];
    const uint32_t sbase = smem_u32(sm);

    const int tid  = threadIdx.x;
    const int warp = tid >> 5;
    const int lane = tid & 31;
    const int qb = blockIdx.x;
    const int h  = blockIdx.y;
    const int g  = h >> 2;

    // --- load Q tile (128 rows x 128 halves), swizzled ---
    {
        const int row = tid >> 1;
        const int cb = (tid & 1) * 8;
        const char* src = (const char*)(qh + ((long)h * T_SEQ + qb * 128 + row) * 128);
#pragma unroll
        for (int c = 0; c < 8; ++c) {
            const int chunk = cb + c;
            const int sw = row * 256 + ((chunk ^ (row & 7)) << 4);
            cp_async16(sm + FL_QS + sw, src + chunk * 16);
        }
        CP_COMMIT();
    }
    // --- stage 0 K/V ---
    {
        const int row = tid >> 2;
        const int cb = (tid & 3) * 4;
        const char* srcK = (const char*)(kh + ((long)g * T_SEQ + row) * 128);
        const char* srcV = (const char*)(vh + ((long)g * T_SEQ + row) * 128);
#pragma unroll
        for (int c = 0; c < 4; ++c) {
            const int chunk = cb + c;
            const int sw = row * 256 + ((chunk ^ (row & 7)) << 4);
            cp_async16(sm + FL_STAGE0 + sw, srcK + chunk * 16);
            cp_async16(sm + FL_STAGE0 + 16384 + sw, srcV + chunk * 16);
        }
        CP_COMMIT();
    }

    // wait for Q only (stage0 still in flight), then ldmatrix Q into registers
    asm volatile("cp.async.wait_group 1;" ::: "memory");
    __syncthreads();

    const int ar = (lane & 7) + ((lane >> 3) & 1) * 8;
    const int ac = lane >> 4;
    uint32_t Qf[8][4];
#pragma unroll
    for (int kb = 0; kb < 8; ++kb) {
        const int qrow = warp * 16 + ar;
        const uint32_t addr = sbase + FL_QS + qrow * 256 + ((((kb << 1) + ac) ^ (qrow & 7)) << 4);
        LDSM4(Qf[kb][0], Qf[kb][1], Qf[kb][2], Qf[kb][3], addr);
    }

    const int br = (lane & 7) + ((lane >> 4) & 1) * 8;
    const int bc = (lane >> 3) & 1;
    const int vr = (lane & 7) + ((lane >> 3) & 1) * 8;
    const int vc = lane >> 4;

    float acc[16][4];
#pragma unroll
    for (int dn = 0; dn < 16; ++dn)
#pragma unroll
        for (int u = 0; u < 4; ++u) acc[dn][u] = 0.f;
    float mrow[2] = {-1e30f, -1e30f};
    float lrow[2] = {0.f, 0.f};

    for (int kt = 0; kt < 32; ++kt) {
        asm volatile("cp.async.wait_group 0;" ::: "memory");
        __syncthreads();
        if (kt + 1 < 32) {
            const int row = tid >> 2;
            const int cb = (tid & 3) * 4;
            char* st = sm + FL_STAGE0 + ((kt + 1) & 1) * FL_STAGEB;
            const char* srcK = (const char*)(kh + ((long)g * T_SEQ + (kt + 1) * 64 + row) * 128);
            const char* srcV = (const char*)(vh + ((long)g * T_SEQ + (kt + 1) * 64 + row) * 128);
#pragma unroll
            for (int c = 0; c < 4; ++c) {
                const int chunk = cb + c;
                const int sw = row * 256 + ((chunk ^ (row & 7)) << 4);
                cp_async16(st + sw, srcK + chunk * 16);
                cp_async16(st + 16384 + sw, srcV + chunk * 16);
            }
            CP_COMMIT();
        }
        const uint32_t Ks = sbase + FL_STAGE0 + (kt & 1) * FL_STAGEB;
        const uint32_t Vs = Ks + 16384;

        // --- S = Q @ K^T : 8 n-tiles (64 keys) ---
        float sacc[8][4];
#pragma unroll
        for (int j = 0; j < 8; ++j)
#pragma unroll
            for (int u = 0; u < 4; ++u) sacc[j][u] = 0.f;
#pragma unroll
        for (int kb = 0; kb < 8; ++kb) {
            uint32_t Bf[4][4];
#pragma unroll
            for (int n16 = 0; n16 < 4; ++n16) {
                const int krow = n16 * 16 + br;
                const uint32_t addr = Ks + krow * 256 + ((((kb << 1) + bc) ^ (krow & 7)) << 4);
                LDSM4(Bf[n16][0], Bf[n16][1], Bf[n16][2], Bf[n16][3], addr);
            }
#pragma unroll
            for (int nt = 0; nt < 8; ++nt)
                mma_fp16(sacc[nt], Qf[kb], Bf[nt >> 1][(nt & 1) * 2], Bf[nt >> 1][(nt & 1) * 2 + 1]);
        }

        // --- online softmax (rows gi and gi+8) ---
#pragma unroll
        for (int rh = 0; rh < 2; ++rh) {
            float tmax = -1e30f;
#pragma unroll
            for (int j = 0; j < 8; ++j)
                tmax = fmaxf(tmax, fmaxf(sacc[j][rh * 2], sacc[j][rh * 2 + 1]));
            tmax = fmaxf(tmax, __shfl_xor_sync(0xffffffffu, tmax, 1));
            tmax = fmaxf(tmax, __shfl_xor_sync(0xffffffffu, tmax, 2));
            const float mnew = fmaxf(mrow[rh], tmax);
            const float corr = __expf(mrow[rh] - mnew);
            float psum = 0.f;
#pragma unroll
            for (int j = 0; j < 8; ++j) {
                const float p0 = __expf(sacc[j][rh * 2] - mnew);
                const float p1 = __expf(sacc[j][rh * 2 + 1] - mnew);
                sacc[j][rh * 2] = p0;
                sacc[j][rh * 2 + 1] = p1;
                psum += p0 + p1;
            }
            psum += __shfl_xor_sync(0xffffffffu, psum, 1);
            psum += __shfl_xor_sync(0xffffffffu, psum, 2);
            lrow[rh] = lrow[rh] * corr + psum;
            mrow[rh] = mnew;
#pragma unroll
            for (int dn = 0; dn < 16; ++dn) {
                acc[dn][rh * 2] *= corr;
                acc[dn][rh * 2 + 1] *= corr;
            }
        }

        // --- P fragments (C-frag layout == A-frag layout) ---
        uint32_t Pa[4][4];
#pragma unroll
        for (int t = 0; t < 4; ++t) {
            Pa[t][0] = pack_f2h(sacc[2 * t][0], sacc[2 * t][1]);
            Pa[t][1] = pack_f2h(sacc[2 * t][2], sacc[2 * t][3]);
            Pa[t][2] = pack_f2h(sacc[2 * t + 1][0], sacc[2 * t + 1][1]);
            Pa[t][3] = pack_f2h(sacc[2 * t + 1][2], sacc[2 * t + 1][3]);
        }

        // --- acc += P @ V (V via ldmatrix.trans) ---
#pragma unroll
        for (int t = 0; t < 4; ++t) {
            const int vrow = t * 16 + vr;
#pragma unroll
            for (int dn16 = 0; dn16 < 8; ++dn16) {
                uint32_t Vt[4];
                const uint32_t addr = Vs + vrow * 256 + ((((dn16 << 1) + vc) ^ (vrow & 7)) << 4);
                LDSM4T(Vt[0], Vt[1], Vt[2], Vt[3], addr);
                mma_fp16(acc[dn16 * 2],     Pa[t], Vt[0], Vt[1]);
                mma_fp16(acc[dn16 * 2 + 1], Pa[t], Vt[2], Vt[3]);
            }
        }
    }

    // --- epilogue: y[t][h*128+d] fp16 ---
    const int gi = lane >> 2;
    const int ci = lane & 3;
    const float il0 = 1.f / lrow[0];
    const float il1 = 1.f / lrow[1];
    const long row0 = (long)qb * 128 + warp * 16 + gi;
    const long row1 = row0 + 8;
#pragma unroll
    for (int dn = 0; dn < 16; ++dn) {
        const long col = h * 128 + dn * 8 + ci * 2;
        *(uint32_t*)(y + row0 * C_EMB + col) = pack_f2h(acc[dn][0] * il0, acc[dn][1] * il0);
        *(uint32_t*)(y + row1 * C_EMB + col) = pack_f2h(acc[dn][2] * il1, acc[dn][3] * il1);
    }
}

// ---------------- host launcher ----------------
extern "C" void kernel_launch(void* const* d_in, const int* in_sizes, int n_in,
                              void* d_out, int out_size) {
    const float* x       = (const float*)d_in[0];
    const float* cosb    = (const float*)d_in[1];
    const float* sinb    = (const float*)d_in[2];
    const float* norm1_w = (const float*)d_in[3];
    const float* norm2_w = (const float*)d_in[4];
    const float* attn_w  = (const float*)d_in[5];
    const float* proj_w  = (const float*)d_in[6];
    const float* scale_w = (const float*)d_in[7];
    const float* scale_b = (const float*)d_in[8];
    const float* gate_w  = (const float*)d_in[9];
    const float* up_w    = (const float*)d_in[10];
    const float* down_w  = (const float*)d_in[11];
    float* out = (float*)d_out;

    float *qkv, *scaling, *scale_t, *resid, *gate;
    cudaGetSymbolAddress((void**)&qkv, g_qkv);
    cudaGetSymbolAddress((void**)&scaling, g_scaling);
    cudaGetSymbolAddress((void**)&scale_t, g_scale_t);
    cudaGetSymbolAddress((void**)&resid, g_resid);
    cudaGetSymbolAddress((void**)&gate, g_gate);

    __half *wq, *ws, *wp, *wg, *wu, *wd, *n1, *n2, *y, *hb, *qh, *kh, *vh;
    cudaGetSymbolAddress((void**)&wq, g_wq);
    cudaGetSymbolAddress((void**)&ws, g_ws);
    cudaGetSymbolAddress((void**)&wp, g_wp);
    cudaGetSymbolAddress((void**)&wg, g_wg);
    cudaGetSymbolAddress((void**)&wu, g_wu);
    cudaGetSymbolAddress((void**)&wd, g_wd);
    cudaGetSymbolAddress((void**)&n1, g_n1);
    cudaGetSymbolAddress((void**)&n2, g_n2);
    cudaGetSymbolAddress((void**)&y, g_y);
    cudaGetSymbolAddress((void**)&hb, g_hb);
    cudaGetSymbolAddress((void**)&qh, g_qh);
    cudaGetSymbolAddress((void**)&kh, g_kh);
    cudaGetSymbolAddress((void**)&vh, g_vh);

    cudaFuncSetAttribute(flash_mma, cudaFuncAttributeMaxDynamicSharedMemorySize, FLASH_SMEM);
    cudaFuncSetAttribute(hgemm<0, 0>, cudaFuncAttributeMaxDynamicSharedMemorySize, GEMM_SMEM);
    cudaFuncSetAttribute(hgemm<1, 0>, cudaFuncAttributeMaxDynamicSharedMemorySize, GEMM_SMEM);
    cudaFuncSetAttribute(hgemm<2, 0>, cudaFuncAttributeMaxDynamicSharedMemorySize, GEMM_SMEM);
    cudaFuncSetAttribute(hgemm<3, 1>, cudaFuncAttributeMaxDynamicSharedMemorySize, GEMM_SMEM);

    // weight converts (fp32 -> fp16)
    cvt_kernel<<<(QKV_N * C_EMB) / 1024, 256>>>(attn_w, wq);
    cvt_kernel<<<(C_EMB * C_EMB) / 1024, 256>>>(scale_w, ws);
    cvt_kernel<<<(C_EMB * C_EMB) / 1024, 256>>>(proj_w, wp);
    cvt_kernel<<<(FFN_N * C_EMB) / 1024, 256>>>(gate_w, wg);
    cvt_kernel<<<(FFN_N * C_EMB) / 1024, 256>>>(up_w, wu);
    cvt_kernel<<<(C_EMB * FFN_N) / 1024, 256>>>(down_w, wd);

    // n1 = rmsnorm(x, norm1_w) -> fp16
    rmsnorm_h<<<T_SEQ, 256>>>(x, norm1_w, n1);
    // qkv = n1 @ attn_w^T (fp32 out)
    hgemm<0, 0><<<dim3(QKV_N / 128, T_SEQ / 128), 256, GEMM_SMEM>>>(
        n1, wq, qkv, nullptr, T_SEQ, QKV_N, C_EMB, nullptr, nullptr);
    // scaling = relu(n1 @ scale_w^T + b) (fp32)
    hgemm<1, 0><<<dim3(C_EMB / 128, T_SEQ / 128), 256, GEMM_SMEM>>>(
        n1, ws, scaling, nullptr, T_SEQ, C_EMB, C_EMB, nullptr, scale_b);
    // per-head score scale
    scale_mean_kernel<<<(T_SEQ * N_HEAD_) / 8, 256>>>(scaling, scale_t);
    // rope + prescale + fp16 Q/K/V planes
    qkv_prep<<<dim3(T_SEQ, 8), 128>>>(qkv, cosb, sinb, scale_t, qh, kh, vh);
    // flash attention -> y fp16
    flash_mma<<<dim3(T_SEQ / 128, N_HEAD_), 256, FLASH_SMEM>>>(qh, kh, vh, y);
    // resid = x + y @ proj_w^T (fp32)
    hgemm<2, 0><<<dim3(C_EMB / 128, T_SEQ / 128), 256, GEMM_SMEM>>>(
        y, wp, resid, nullptr, T_SEQ, C_EMB, C_EMB, x, nullptr);
    // n2 = rmsnorm(resid) -> fp16
    rmsnorm_h<<<T_SEQ, 256>>>(resid, norm2_w, n2);
    // gate = n2 @ gate_w^T (fp32)
    hgemm<0, 0><<<dim3(FFN_N / 128, T_SEQ / 128), 256, GEMM_SMEM>>>(
        n2, wg, gate, nullptr, T_SEQ, FFN_N, C_EMB, nullptr, nullptr);
    // hbuf = silu(gate) * (n2 @ up_w^T) -> fp16
    hgemm<3, 1><<<dim3(FFN_N / 128, T_SEQ / 128), 256, GEMM_SMEM>>>(
        n2, wu, nullptr, hb, T_SEQ, FFN_N, C_EMB, gate, nullptr);
    // out = resid + hbuf @ down_w^T (fp32)
    hgemm<2, 0><<<dim3(C_EMB / 128, T_SEQ / 128), 256, GEMM_SMEM>>>(
        hb, wd, out, nullptr, T_SEQ, C_EMB, FFN_N, resid, nullptr);
}